// round 13
// baseline (speedup 1.0000x reference)
#include <cuda_runtime.h>
#include <cuda_bf16.h>
#include <cstdint>

// out = feat @ Wv + bv
//
// The reference's softmax over axis=-2 (j) followed by einsum('ijk,ik->ik')
// (a sum over j) makes the attention-weight branch sum to exactly 1 per
// (i,k), so out[i,k] == v[i,k] == (feat @ Wv + bv)[i,k].
//
// feat: [N=1024, C=256] f32   (d_in[0])
// Wv:   [C, C]          f32   (d_in[9])
// bv:   [C]             f32   (d_in[10])
// out:  [N, C]          f32
//
// R13: two-kernel graph.
//  K1: split f32 -> bf16 hi/lo ONCE, written to __device__ scratch in
//      canonical mma.m16n8k16 fragment order (no per-CTA redundant convert).
//  K2: smem-free, sync-free GEMM: coalesced LDG of fragments (L2-hot) +
//      mma.sync.bf16;  A*B ~= Ah*Bh + Ah*Bl + Al*Bh  (fp32 accum).

namespace {

constexpr int Cdim = 256;
constexpr int MT   = 64;   // 1024/16 m-tiles
constexpr int NT   = 32;   // 256/8  n-tiles
constexpr int KS   = 16;   // 256/16 k-steps

// fragment scratch: A = [mt][ks][lane][4] u32 (as uint4), B = [nt][ks][lane][2] (uint2)
__device__ uint4 g_fa_hi[MT * KS * 32];
__device__ uint4 g_fa_lo[MT * KS * 32];
__device__ uint2 g_fb_hi[NT * KS * 32];
__device__ uint2 g_fb_lo[NT * KS * 32];

#define MMA_BF16(c, a0, a1, a2, a3, b0, b1)                                  \
    asm volatile("mma.sync.aligned.m16n8k16.row.col.f32.bf16.bf16.f32 "      \
                 "{%0,%1,%2,%3}, {%4,%5,%6,%7}, {%8,%9}, {%0,%1,%2,%3};"     \
                 : "+f"((c)[0]), "+f"((c)[1]), "+f"((c)[2]), "+f"((c)[3])    \
                 : "r"(a0), "r"(a1), "r"(a2), "r"(a3), "r"(b0), "r"(b1))

// pack two floats to bf16x2: low half = first element (validated R11/12)
__device__ __forceinline__ uint32_t pack_bf2(float a, float b) {
    uint32_t r;
    asm("cvt.rn.bf16x2.f32 %0, %1, %2;" : "=r"(r) : "f"(b), "f"(a));
    return r;
}
// split 2 floats -> hi bf16x2 + lo (residual) bf16x2
__device__ __forceinline__ void split2(float x, float y,
                                       uint32_t& hi, uint32_t& lo) {
    hi = pack_bf2(x, y);
    const float hx = __uint_as_float(hi << 16);
    const float hy = __uint_as_float(hi & 0xFFFF0000u);
    lo = pack_bf2(x - hx, y - hy);
}

// ---------------- Kernel 1: convert + fragment-swizzle ----------------
// blocks [0,128): A-part, 32768 threads = (mt, ks, lane)
// blocks [128,192): B-part, 16384 threads = (nt, ks, lane)
__global__ __launch_bounds__(256)
void convert_kernel(const float* __restrict__ feat,
                    const float* __restrict__ Wv)
{
    const int t = (int)(blockIdx.x * 256 + threadIdx.x);
    if (t < MT * KS * 32) {
        const int lane = t & 31;
        const int ks   = (t >> 5) & 15;
        const int mt   = t >> 9;
        const int g    = lane >> 2;
        const int c0   = ks * 16 + (lane & 3) * 2;
        const int r0   = mt * 16 + g;
        const int r1   = r0 + 8;

        const float2 x0 = *reinterpret_cast<const float2*>(&feat[r0 * Cdim + c0]);
        const float2 x1 = *reinterpret_cast<const float2*>(&feat[r1 * Cdim + c0]);
        const float2 x2 = *reinterpret_cast<const float2*>(&feat[r0 * Cdim + c0 + 8]);
        const float2 x3 = *reinterpret_cast<const float2*>(&feat[r1 * Cdim + c0 + 8]);

        uint4 hi, lo;
        split2(x0.x, x0.y, hi.x, lo.x);
        split2(x1.x, x1.y, hi.y, lo.y);
        split2(x2.x, x2.y, hi.z, lo.z);
        split2(x3.x, x3.y, hi.w, lo.w);

        const int idx = (mt * KS + ks) * 32 + lane;
        g_fa_hi[idx] = hi;
        g_fa_lo[idx] = lo;
    } else {
        const int t2 = t - MT * KS * 32;
        if (t2 >= NT * KS * 32) return;
        const int lane = t2 & 31;
        const int ks   = (t2 >> 5) & 15;
        const int nt   = t2 >> 9;
        const int n    = nt * 8 + (lane >> 2);
        const int k0   = ks * 16 + (lane & 3) * 2;

        const float b00 = Wv[(k0    ) * Cdim + n];
        const float b01 = Wv[(k0 + 1) * Cdim + n];
        const float b10 = Wv[(k0 + 8) * Cdim + n];
        const float b11 = Wv[(k0 + 9) * Cdim + n];

        uint2 hi, lo;
        split2(b00, b01, hi.x, lo.x);
        split2(b10, b11, hi.y, lo.y);

        const int idx = (nt * KS + ks) * 32 + lane;
        g_fb_hi[idx] = hi;
        g_fb_lo[idx] = lo;
    }
}

// ---------------- Kernel 2: smem-free tensor-core GEMM ----------------
// 128 CTAs x 8 warps = 1024 warps; warp w -> (mt = w>>4, ntpair = w&15).
// Each warp computes a 16(M) x 16(N) output tile (2 n8 tiles), K = 256.
__global__ __launch_bounds__(256, 1)
void gemm_kernel(const float* __restrict__ bias,
                 float* __restrict__ O)
{
    const int lane = (int)(threadIdx.x & 31);
    const int wid  = (int)(blockIdx.x * 8 + (threadIdx.x >> 5));
    const int mt   = wid >> 4;
    const int nt0  = (wid & 15) * 2;
    const int nt1  = nt0 + 1;

    const uint4* pAh = &g_fa_hi[(mt * KS) * 32 + lane];
    const uint4* pAl = &g_fa_lo[(mt * KS) * 32 + lane];
    const uint2* pB0h = &g_fb_hi[(nt0 * KS) * 32 + lane];
    const uint2* pB0l = &g_fb_lo[(nt0 * KS) * 32 + lane];
    const uint2* pB1h = &g_fb_hi[(nt1 * KS) * 32 + lane];
    const uint2* pB1l = &g_fb_lo[(nt1 * KS) * 32 + lane];

    float acc0[4] = {0.f, 0.f, 0.f, 0.f};
    float acc1[4] = {0.f, 0.f, 0.f, 0.f};

    #pragma unroll 4
    for (int ks = 0; ks < KS; ks++) {
        const uint4 ah  = pAh [ks * 32];
        const uint4 al  = pAl [ks * 32];
        const uint2 b0h = pB0h[ks * 32];
        const uint2 b0l = pB0l[ks * 32];
        const uint2 b1h = pB1h[ks * 32];
        const uint2 b1l = pB1l[ks * 32];

        MMA_BF16(acc0, ah.x, ah.y, ah.z, ah.w, b0h.x, b0h.y);
        MMA_BF16(acc0, ah.x, ah.y, ah.z, ah.w, b0l.x, b0l.y);
        MMA_BF16(acc0, al.x, al.y, al.z, al.w, b0h.x, b0h.y);
        MMA_BF16(acc1, ah.x, ah.y, ah.z, ah.w, b1h.x, b1h.y);
        MMA_BF16(acc1, ah.x, ah.y, ah.z, ah.w, b1l.x, b1l.y);
        MMA_BF16(acc1, al.x, al.y, al.z, al.w, b1h.x, b1h.y);
    }

    // ---- epilogue: bias add + float2 stores (canonical D mapping) ----
    const int g  = lane >> 2;
    const int tc = (lane & 3) * 2;
    const int r1 = mt * 16 + g;
    const int r2 = r1 + 8;

    {
        const int n = nt0 * 8 + tc;
        const float2 bb = *reinterpret_cast<const float2*>(&bias[n]);
        float2 o1 = make_float2(acc0[0] + bb.x, acc0[1] + bb.y);
        float2 o2 = make_float2(acc0[2] + bb.x, acc0[3] + bb.y);
        *reinterpret_cast<float2*>(&O[r1 * Cdim + n]) = o1;
        *reinterpret_cast<float2*>(&O[r2 * Cdim + n]) = o2;
    }
    {
        const int n = nt1 * 8 + tc;
        const float2 bb = *reinterpret_cast<const float2*>(&bias[n]);
        float2 o1 = make_float2(acc1[0] + bb.x, acc1[1] + bb.y);
        float2 o2 = make_float2(acc1[2] + bb.x, acc1[3] + bb.y);
        *reinterpret_cast<float2*>(&O[r1 * Cdim + n]) = o1;
        *reinterpret_cast<float2*>(&O[r2 * Cdim + n]) = o2;
    }
}

} // namespace

extern "C" void kernel_launch(void* const* d_in, const int* in_sizes, int n_in,
                              void* d_out, int out_size)
{
    const float* feat = (const float*)d_in[0];
    const float* Wv   = (const float*)d_in[9];
    const float* bv   = (const float*)d_in[10];
    float* out        = (float*)d_out;

    convert_kernel<<<192, 256>>>(feat, Wv);   // 32768 A-threads + 16384 B-threads
    gemm_kernel<<<128, 256>>>(bv, out);       // 1024 warps, smem-free
}

// round 14
// speedup vs baseline: 1.2214x; 1.2214x over previous
#include <cuda_runtime.h>
#include <cuda_bf16.h>
#include <cstdint>

// out = feat @ Wv + bv
//
// The reference's softmax over axis=-2 (j) followed by einsum('ijk,ik->ik')
// (a sum over j) makes the attention-weight branch sum to exactly 1 per
// (i,k), so out[i,k] == v[i,k] == (feat @ Wv + bv)[i,k].
//
// feat: [N=1024, C=256] f32   (d_in[0])
// Wv:   [C, C]          f32   (d_in[9])
// bv:   [C]             f32   (d_in[10])
// out:  [N, C]          f32
//
// R14: K1 converts f32 -> bf16 hi/lo ONCE (linear layout, ~0.7us).
//      K2 = R12's validated smem+ldmatrix+mma.bf16 GEMM, but its load phase
//      is 24 cp.async 16B copies/thread (no registers, no convert math).
//      Split precision: A*B ~= Ah*Bh + Ah*Bl + Al*Bh (fp32 accum).

namespace {

constexpr int Cdim = 256;

// ---- bf16 hi/lo scratch (linear) ----
__device__ __nv_bfloat16 g_a_hi[1024 * 256];
__device__ __nv_bfloat16 g_a_lo[1024 * 256];
__device__ __nv_bfloat16 g_b_hi[256 * 256];   // [k][n], same layout as Wv
__device__ __nv_bfloat16 g_b_lo[256 * 256];

// ---- K2 smem layout (identical strides to R12; ldmatrix conflict-free) ----
constexpr uint32_t A_STRIDE_B = 528;   // 264 bf16 per row
constexpr uint32_t B_STRIDE_B = 80;    // 40 bf16 per row
constexpr uint32_t SM_AHI  = 0;
constexpr uint32_t SM_ALO  = SM_AHI + 64 * A_STRIDE_B;    // 33792
constexpr uint32_t SM_BHI  = SM_ALO + 64 * A_STRIDE_B;    // 67584
constexpr uint32_t SM_BLO  = SM_BHI + 256 * B_STRIDE_B;   // 88064
constexpr uint32_t SM_BIAS = SM_BLO + 256 * B_STRIDE_B;   // 108544
constexpr uint32_t SMEM_BYTES = SM_BIAS + 128;            // 108672

#define LDSM_X4(r0, r1, r2, r3, addr)                                        \
    asm volatile("ldmatrix.sync.aligned.m8n8.x4.shared.b16 {%0,%1,%2,%3}, [%4];" \
                 : "=r"(r0), "=r"(r1), "=r"(r2), "=r"(r3) : "r"(addr))

#define LDSM_X2T(r0, r1, addr)                                               \
    asm volatile("ldmatrix.sync.aligned.m8n8.x2.trans.shared.b16 {%0,%1}, [%2];" \
                 : "=r"(r0), "=r"(r1) : "r"(addr))

#define MMA_BF16(c, a0, a1, a2, a3, b0, b1)                                  \
    asm volatile("mma.sync.aligned.m16n8k16.row.col.f32.bf16.bf16.f32 "      \
                 "{%0,%1,%2,%3}, {%4,%5,%6,%7}, {%8,%9}, {%0,%1,%2,%3};"     \
                 : "+f"((c)[0]), "+f"((c)[1]), "+f"((c)[2]), "+f"((c)[3])    \
                 : "r"(a0), "r"(a1), "r"(a2), "r"(a3), "r"(b0), "r"(b1))

#define CP_ASYNC16(dst, src)                                                 \
    asm volatile("cp.async.ca.shared.global [%0], [%1], 16;"                 \
                 :: "r"(dst), "l"(src) : "memory")

__device__ __forceinline__ uint32_t smem_u32(const void* p) {
    uint32_t a;
    asm("{ .reg .u64 t; cvta.to.shared.u64 t, %1; cvt.u32.u64 %0, t; }"
        : "=r"(a) : "l"(p));
    return a;
}

__device__ __forceinline__ uint32_t pack_bf2(float a, float b) {
    uint32_t r;
    asm("cvt.rn.bf16x2.f32 %0, %1, %2;" : "=r"(r) : "f"(b), "f"(a));
    return r;
}
__device__ __forceinline__ void split4(float4 f, uint2& hi, uint2& lo) {
    hi.x = pack_bf2(f.x, f.y);
    hi.y = pack_bf2(f.z, f.w);
    const float hx = __uint_as_float(hi.x << 16);
    const float hy = __uint_as_float(hi.x & 0xFFFF0000u);
    const float hz = __uint_as_float(hi.y << 16);
    const float hw = __uint_as_float(hi.y & 0xFFFF0000u);
    lo.x = pack_bf2(f.x - hx, f.y - hy);
    lo.y = pack_bf2(f.z - hz, f.w - hw);
}

// ---------------- K1: one-shot f32 -> bf16 hi/lo convert ----------------
// 81920 threads: [0,65536) feat float4s, [65536,81920) Wv float4s.
__global__ __launch_bounds__(256)
void convert_kernel(const float* __restrict__ feat,
                    const float* __restrict__ Wv)
{
    const int t = (int)(blockIdx.x * 256 + threadIdx.x);
    if (t < 65536) {
        const float4 f = reinterpret_cast<const float4*>(feat)[t];
        uint2 hi, lo;
        split4(f, hi, lo);
        reinterpret_cast<uint2*>(g_a_hi)[t] = hi;
        reinterpret_cast<uint2*>(g_a_lo)[t] = lo;
    } else {
        const int t2 = t - 65536;
        const float4 f = reinterpret_cast<const float4*>(Wv)[t2];
        uint2 hi, lo;
        split4(f, hi, lo);
        reinterpret_cast<uint2*>(g_b_hi)[t2] = hi;
        reinterpret_cast<uint2*>(g_b_lo)[t2] = lo;
    }
}

// ---------------- K2: smem + ldmatrix + mma GEMM (R12 mainloop) ----------
// CTA: 64(M) x 32(N), full K=256. 256 threads = 8 warps.
// Warp w: m-strip (w>>1)*16, column-half (w&1). Grid (8,16) = 128 CTAs.
__global__ __launch_bounds__(256, 1)
void gemm_kernel(const float* __restrict__ bias,
                 float* __restrict__ O)
{
    extern __shared__ char smem[];
    const uint32_t sb = smem_u32(smem);

    const int tid  = (int)threadIdx.x;   // 0..255
    const int warp = tid >> 5;
    const int lane = tid & 31;
    const int row0 = (int)blockIdx.y * 64;
    const int col0 = (int)blockIdx.x * 32;

    // ---- cp.async tile fill: A hi/lo 8+8 chunks, B hi/lo 4+4 chunks ----
    // A: 64 rows x 256 bf16 = 32 x 16B chunks per row; 2048 chunks/buffer.
    #pragma unroll
    for (int it = 0; it < 8; it++) {
        const int idx = it * 256 + tid;     // 0..2047
        const int m   = idx >> 5;
        const int c   = idx & 31;
        const __nv_bfloat16* srcH = &g_a_hi[(row0 + m) * Cdim + c * 8];
        const __nv_bfloat16* srcL = &g_a_lo[(row0 + m) * Cdim + c * 8];
        const uint32_t d = (uint32_t)m * A_STRIDE_B + (uint32_t)c * 16;
        CP_ASYNC16(sb + SM_AHI + d, srcH);
        CP_ASYNC16(sb + SM_ALO + d, srcL);
    }
    // B: 256 k-rows x 32 bf16 = 4 x 16B chunks per row; 1024 chunks/buffer.
    #pragma unroll
    for (int it = 0; it < 4; it++) {
        const int idx = it * 256 + tid;     // 0..1023
        const int k   = idx >> 2;
        const int c   = idx & 3;
        const __nv_bfloat16* srcH = &g_b_hi[k * Cdim + col0 + c * 8];
        const __nv_bfloat16* srcL = &g_b_lo[k * Cdim + col0 + c * 8];
        const uint32_t d = (uint32_t)k * B_STRIDE_B + (uint32_t)c * 16;
        CP_ASYNC16(sb + SM_BHI + d, srcH);
        CP_ASYNC16(sb + SM_BLO + d, srcL);
    }
    asm volatile("cp.async.commit_group;" ::: "memory");

    // stage bias while copies fly
    if (tid < 8) {
        reinterpret_cast<float4*>(smem + SM_BIAS)[tid] =
            reinterpret_cast<const float4*>(bias + col0)[tid];
    }

    asm volatile("cp.async.wait_group 0;" ::: "memory");
    __syncthreads();

    // ---- tensor-core mainloop (identical to R12) ----
    const int m0 = (warp >> 1) * 16;
    const int nh = (warp & 1) * 32;
    float acc[2][4];
    #pragma unroll
    for (int t = 0; t < 2; t++)
        #pragma unroll
        for (int i = 0; i < 4; i++) acc[t][i] = 0.f;

    const uint32_t aHiBase = sb + SM_AHI +
        (uint32_t)(m0 + (lane & 15)) * A_STRIDE_B + (uint32_t)(lane >> 4) * 16;
    const uint32_t aLoBase = aHiBase + (SM_ALO - SM_AHI);
    const uint32_t bHiBase = sb + SM_BHI +
        (uint32_t)(lane & 15) * B_STRIDE_B + (uint32_t)nh;

    #pragma unroll
    for (int ks = 0; ks < 16; ks++) {
        uint32_t ah0, ah1, ah2, ah3, al0, al1, al2, al3;
        LDSM_X4(ah0, ah1, ah2, ah3, aHiBase + (uint32_t)ks * 32);
        LDSM_X4(al0, al1, al2, al3, aLoBase + (uint32_t)ks * 32);

        const uint32_t bk = bHiBase + (uint32_t)ks * (16 * B_STRIDE_B);
        #pragma unroll
        for (int t = 0; t < 2; t++) {
            uint32_t bh0, bh1, bl0, bl1;
            const uint32_t ba = bk + (uint32_t)t * 16;
            LDSM_X2T(bh0, bh1, ba);
            LDSM_X2T(bl0, bl1, ba + (SM_BLO - SM_BHI));
            MMA_BF16(acc[t], ah0, ah1, ah2, ah3, bh0, bh1);
            MMA_BF16(acc[t], ah0, ah1, ah2, ah3, bl0, bl1);
            MMA_BF16(acc[t], al0, al1, al2, al3, bh0, bh1);
        }
    }

    // ---- epilogue: bias add + stores (canonical m16n8 D mapping) ----
    const float* bs = reinterpret_cast<const float*>(smem + SM_BIAS);
    const int g  = lane >> 2;
    const int tc = (lane & 3) * 2;
    const int r1 = row0 + m0 + g;
    const int r2 = r1 + 8;
    const int nb = (warp & 1) * 16;
    #pragma unroll
    for (int t = 0; t < 2; t++) {
        const int n = nb + t * 8 + tc;
        float2 o1, o2;
        o1.x = acc[t][0] + bs[n];
        o1.y = acc[t][1] + bs[n + 1];
        o2.x = acc[t][2] + bs[n];
        o2.y = acc[t][3] + bs[n + 1];
        *reinterpret_cast<float2*>(&O[r1 * Cdim + col0 + n]) = o1;
        *reinterpret_cast<float2*>(&O[r2 * Cdim + col0 + n]) = o2;
    }
}

} // namespace

extern "C" void kernel_launch(void* const* d_in, const int* in_sizes, int n_in,
                              void* d_out, int out_size)
{
    const float* feat = (const float*)d_in[0];
    const float* Wv   = (const float*)d_in[9];
    const float* bv   = (const float*)d_in[10];
    float* out        = (float*)d_out;

    cudaFuncSetAttribute(gemm_kernel,
                         cudaFuncAttributeMaxDynamicSharedMemorySize,
                         (int)SMEM_BYTES);

    convert_kernel<<<320, 256>>>(feat, Wv);          // one-shot hi/lo split
    dim3 grid(8, 16);                                // 128 CTAs, one wave
    gemm_kernel<<<grid, 256, SMEM_BYTES>>>(bv, out);
}

// round 15
// speedup vs baseline: 1.2620x; 1.0332x over previous
#include <cuda_runtime.h>
#include <cuda_bf16.h>
#include <cstdint>

// out = feat @ Wv + bv
//
// The reference's softmax over axis=-2 (j) followed by einsum('ijk,ik->ik')
// (a sum over j) makes the attention-weight branch sum to exactly 1 per
// (i,k), so out[i,k] == v[i,k] == (feat @ Wv + bv)[i,k].
//
// feat: [N=1024, C=256] f32   (d_in[0])
// Wv:   [C, C]          f32   (d_in[9])
// bv:   [C]             f32   (d_in[10])
// out:  [N, C]          f32
//
// Split precision on tensor cores (tcgen05 rejected by compute_103):
//   x ~= hi + lo (bf16);  A*B ~= Ah*Bh + Ah*Bl + Al*Bh   (fp32 accum)
// R15: R12's fused smem+ldmatrix+mma kernel with 32x32 tiles and 256 CTAs
// (~2 CTAs/SM) so the load+convert fill of one CTA overlaps the MMA phase
// of the other — attacking the exposed-latency fill that bound R11-R14.

namespace {

constexpr int Cdim = 256;

// smem strides (ldmatrix conflict-free, validated R12):
//  A rows 264 bf16 = 528 B; B rows 40 bf16 = 80 B
constexpr uint32_t A_STRIDE_B = 528;
constexpr uint32_t B_STRIDE_B = 80;
constexpr uint32_t SM_AHI  = 0;
constexpr uint32_t SM_ALO  = SM_AHI + 32 * A_STRIDE_B;    // 16896
constexpr uint32_t SM_BHI  = SM_ALO + 32 * A_STRIDE_B;    // 33792
constexpr uint32_t SM_BLO  = SM_BHI + 256 * B_STRIDE_B;   // 54272
constexpr uint32_t SM_BIAS = SM_BLO + 256 * B_STRIDE_B;   // 74752
constexpr uint32_t SMEM_BYTES = SM_BIAS + 128;            // 74880 (2/SM fits)

#define LDSM_X4(r0, r1, r2, r3, addr)                                        \
    asm volatile("ldmatrix.sync.aligned.m8n8.x4.shared.b16 {%0,%1,%2,%3}, [%4];" \
                 : "=r"(r0), "=r"(r1), "=r"(r2), "=r"(r3) : "r"(addr))

#define LDSM_X2T(r0, r1, addr)                                               \
    asm volatile("ldmatrix.sync.aligned.m8n8.x2.trans.shared.b16 {%0,%1}, [%2];" \
                 : "=r"(r0), "=r"(r1) : "r"(addr))

#define MMA_BF16(c, a0, a1, a2, a3, b0, b1)                                  \
    asm volatile("mma.sync.aligned.m16n8k16.row.col.f32.bf16.bf16.f32 "      \
                 "{%0,%1,%2,%3}, {%4,%5,%6,%7}, {%8,%9}, {%0,%1,%2,%3};"     \
                 : "+f"((c)[0]), "+f"((c)[1]), "+f"((c)[2]), "+f"((c)[3])    \
                 : "r"(a0), "r"(a1), "r"(a2), "r"(a3), "r"(b0), "r"(b1))

__device__ __forceinline__ uint32_t smem_u32(const void* p) {
    uint32_t a;
    asm("{ .reg .u64 t; cvta.to.shared.u64 t, %1; cvt.u32.u64 %0, t; }"
        : "=r"(a) : "l"(p));
    return a;
}

__device__ __forceinline__ uint32_t pack_bf2(float a, float b) {
    uint32_t r;
    asm("cvt.rn.bf16x2.f32 %0, %1, %2;" : "=r"(r) : "f"(b), "f"(a));
    return r;
}
// split a float4 into hi (bf16x2 pair) and lo (residual bf16x2 pair)
__device__ __forceinline__ void split4(float4 f, uint2& hi, uint2& lo) {
    hi.x = pack_bf2(f.x, f.y);
    hi.y = pack_bf2(f.z, f.w);
    const float hx = __uint_as_float(hi.x << 16);
    const float hy = __uint_as_float(hi.x & 0xFFFF0000u);
    const float hz = __uint_as_float(hi.y << 16);
    const float hw = __uint_as_float(hi.y & 0xFFFF0000u);
    lo.x = pack_bf2(f.x - hx, f.y - hy);
    lo.y = pack_bf2(f.z - hz, f.w - hw);
}

// CTA: 32(M) x 32(N) tile, full K=256. 128 threads = 4 warps.
// Warp w: m-strip (w>>1)*16, column-half (w&1)*16 (2 n8 fragments).
// Grid (8, 32) = 256 CTAs -> ~2 CTAs/SM for fill/compute overlap.

__global__ __launch_bounds__(128, 2)
void vgemm_mma_kernel(const float* __restrict__ feat,  // [1024, 256]
                      const float* __restrict__ Wv,    // [256, 256]
                      const float* __restrict__ bias,  // [256]
                      float* __restrict__ O)           // [1024, 256]
{
    extern __shared__ char smem[];
    const uint32_t sb = smem_u32(smem);

    const int tid  = (int)threadIdx.x;   // 0..127
    const int warp = tid >> 5;
    const int lane = tid & 31;
    const int row0 = (int)blockIdx.y * 32;
    const int col0 = (int)blockIdx.x * 32;

    // ---- stage bias ----
    if (tid < 8) {
        reinterpret_cast<float4*>(smem + SM_BIAS)[tid] =
            reinterpret_cast<const float4*>(bias + col0)[tid];
    }

    // ---- load + split A: 32 x 256 f32 = 2048 float4; 16 per thread ----
    #pragma unroll
    for (int it = 0; it < 16; it++) {
        const int idx = it * 128 + tid;
        const int m   = idx >> 6;          // 64 float4 per row
        const int c4  = idx & 63;
        const float4 f = *reinterpret_cast<const float4*>(
            &feat[(row0 + m) * Cdim + c4 * 4]);
        uint2 hi, lo;
        split4(f, hi, lo);
        const uint32_t off = (uint32_t)m * A_STRIDE_B + (uint32_t)c4 * 8;
        *reinterpret_cast<uint2*>(smem + SM_AHI + off) = hi;
        *reinterpret_cast<uint2*>(smem + SM_ALO + off) = lo;
    }

    // ---- load + split B: Wv[k][col0..col0+32), 2048 float4; 16 per thread ----
    #pragma unroll
    for (int it = 0; it < 16; it++) {
        const int idx = it * 128 + tid;
        const int k   = idx >> 3;          // 8 float4 per row
        const int c4  = idx & 7;
        const float4 f = *reinterpret_cast<const float4*>(
            &Wv[k * Cdim + col0 + c4 * 4]);
        uint2 hi, lo;
        split4(f, hi, lo);
        const uint32_t off = (uint32_t)k * B_STRIDE_B + (uint32_t)c4 * 8;
        *reinterpret_cast<uint2*>(smem + SM_BHI + off) = hi;
        *reinterpret_cast<uint2*>(smem + SM_BLO + off) = lo;
    }

    __syncthreads();

    // ---- tensor-core mainloop ----
    const int m0 = (warp >> 1) * 16;        // m-strip: 0 or 16
    const int nh = (warp & 1) * 32;         // column-half byte offset
    float acc[2][4];
    #pragma unroll
    for (int t = 0; t < 2; t++)
        #pragma unroll
        for (int i = 0; i < 4; i++) acc[t][i] = 0.f;

    const uint32_t aHiBase = sb + SM_AHI +
        (uint32_t)(m0 + (lane & 15)) * A_STRIDE_B + (uint32_t)(lane >> 4) * 16;
    const uint32_t aLoBase = aHiBase + (SM_ALO - SM_AHI);
    const uint32_t bHiBase = sb + SM_BHI +
        (uint32_t)(lane & 15) * B_STRIDE_B + (uint32_t)nh;

    #pragma unroll
    for (int ks = 0; ks < 16; ks++) {
        uint32_t ah0, ah1, ah2, ah3, al0, al1, al2, al3;
        LDSM_X4(ah0, ah1, ah2, ah3, aHiBase + (uint32_t)ks * 32);
        LDSM_X4(al0, al1, al2, al3, aLoBase + (uint32_t)ks * 32);

        const uint32_t bk = bHiBase + (uint32_t)ks * (16 * B_STRIDE_B);
        #pragma unroll
        for (int t = 0; t < 2; t++) {
            uint32_t bh0, bh1, bl0, bl1;
            const uint32_t ba = bk + (uint32_t)t * 16;   // n8 tile -> 16 B
            LDSM_X2T(bh0, bh1, ba);
            LDSM_X2T(bl0, bl1, ba + (SM_BLO - SM_BHI));
            MMA_BF16(acc[t], ah0, ah1, ah2, ah3, bh0, bh1);
            MMA_BF16(acc[t], ah0, ah1, ah2, ah3, bl0, bl1);
            MMA_BF16(acc[t], al0, al1, al2, al3, bh0, bh1);
        }
    }

    // ---- epilogue: bias add + stores (canonical m16n8 D mapping) ----
    const float* bs = reinterpret_cast<const float*>(smem + SM_BIAS);
    const int g  = lane >> 2;
    const int tc = (lane & 3) * 2;
    const int r1 = row0 + m0 + g;
    const int r2 = r1 + 8;
    const int nb = (warp & 1) * 16;
    #pragma unroll
    for (int t = 0; t < 2; t++) {
        const int n = nb + t * 8 + tc;
        float2 o1, o2;
        o1.x = acc[t][0] + bs[n];
        o1.y = acc[t][1] + bs[n + 1];
        o2.x = acc[t][2] + bs[n];
        o2.y = acc[t][3] + bs[n + 1];
        *reinterpret_cast<float2*>(&O[r1 * Cdim + col0 + n]) = o1;
        *reinterpret_cast<float2*>(&O[r2 * Cdim + col0 + n]) = o2;
    }
}

} // namespace

extern "C" void kernel_launch(void* const* d_in, const int* in_sizes, int n_in,
                              void* d_out, int out_size)
{
    const float* feat = (const float*)d_in[0];
    const float* Wv   = (const float*)d_in[9];
    const float* bv   = (const float*)d_in[10];
    float* out        = (float*)d_out;

    cudaFuncSetAttribute(vgemm_mma_kernel,
                         cudaFuncAttributeMaxDynamicSharedMemorySize,
                         (int)SMEM_BYTES);
    dim3 grid(8, 32);   // 8 N-tiles x 32 M-tiles = 256 CTAs (~2/SM)
    vgemm_mma_kernel<<<grid, 128, SMEM_BYTES>>>(feat, Wv, bv, out);
}